// round 10
// baseline (speedup 1.0000x reference)
#include <cuda_runtime.h>
#include <cuda_fp16.h>

#define NQ 20
typedef unsigned long long u64;
typedef unsigned int u32;

// 64MB scratch: fp16x2 intermediate for all 16 batches (fits 126MB L2)
__device__ u32 g_scratch[16u << 20];

// ---------------- f32x2 helpers (packed 2xfp32 ops, sm_103a) ----------------
__device__ __forceinline__ u64 pk(float lo, float hi) {
    u64 r; asm("mov.b64 %0,{%1,%2};" : "=l"(r) : "f"(lo), "f"(hi)); return r;
}
__device__ __forceinline__ void upk(u64 p, float& lo, float& hi) {
    asm("mov.b64 {%0,%1},%2;" : "=f"(lo), "=f"(hi) : "l"(p));
}
__device__ __forceinline__ u64 f2mul(u64 a, u64 b) {
    u64 r; asm("mul.rn.f32x2 %0,%1,%2;" : "=l"(r) : "l"(a), "l"(b)); return r;
}
__device__ __forceinline__ u64 f2fma(u64 a, u64 b, u64 c) {
    u64 r; asm("fma.rn.f32x2 %0,%1,%2,%3;" : "=l"(r) : "l"(a), "l"(b), "l"(c)); return r;
}

// ---------------- fast-Givens RX stages ----------------
// Unscaled update with t = tan(th/2):
//   ax' = ax + t*by ; ay' = ay - t*bx ; bx' = bx + t*ay ; by' = by - t*ax
// True result = (prod of cos) * unscaled; scale applied once at the end.

// intra-pack stage (element mask 1), scalar fma on the halves
template<int NP>
__device__ __forceinline__ void fg_stage0(u64* PX, u64* PY, float tt)
{
#pragma unroll
    for (int q = 0; q < NP; ++q) {
        float xl, xh, yl, yh;
        upk(PX[q], xl, xh); upk(PY[q], yl, yh);
        PX[q] = pk(fmaf(tt, yh, xl), fmaf(tt, yl, xh));
        PY[q] = pk(fmaf(-tt, xh, yl), fmaf(-tt, xl, yh));
    }
}

// one pack-level stage with pack mask pm
template<int NP>
__device__ __forceinline__ void fg_mask(u64* PX, u64* PY, float tv, int pm)
{
    u64 t2  = pk(tv,  tv);
    u64 tn2 = pk(-tv, -tv);
#pragma unroll
    for (int q = 0; q < NP; ++q) {
        if (!(q & pm)) {
            const int q2 = q | pm;
            u64 ax = PX[q], bx = PX[q2];
            PX[q]  = f2fma(t2,  PY[q2], ax);
            PX[q2] = f2fma(t2,  PY[q],  bx);
            PY[q]  = f2fma(tn2, bx, PY[q]);
            PY[q2] = f2fma(tn2, ax, PY[q2]);
        }
    }
}

// stages 1..JMAX (element bits 1..JMAX within the in-register index)
template<int NP, int JMAX>
__device__ __forceinline__ void fg_tail(u64* PX, u64* PY, const float* t)
{
#pragma unroll
    for (int j = 1; j <= JMAX; ++j)
        fg_mask<NP>(PX, PY, t[j], 1 << (j - 1));
}

template<int NP>
__device__ __forceinline__ void fg_scale(u64* PX, u64* PY, float C)
{
    u64 C2 = pk(C, C);
#pragma unroll
    for (int q = 0; q < NP; ++q) {
        PX[q] = f2mul(C2, PX[q]);
        PY[q] = f2mul(C2, PY[q]);
    }
}

// qubit i = most-significant bit => global bit g maps to theta index (19-g)
template<int N>
__device__ __forceinline__ float load_tc(const float* __restrict__ thetas, int b,
                                         int gbase, float* t)
{
    float C = 1.0f;
#pragma unroll
    for (int j = 0; j < N; ++j) {
        float th = thetas[b * NQ + (NQ - 1 - (gbase + j))];
        float s, c;
        __sincosf(0.5f * th, &s, &c);
        t[j] = __fdividef(s, c);
        C *= c;
    }
    return C;
}

// ---------------------------------------------------------------------------
// Pass A (unchanged from the 70.4us config): global bits 0..9, all 16
// batches. Warp owns 1024 contiguous elements. phi streamed in (__ldcs);
// fp16x2 intermediate to scratch (default policy: L2-resident for pass B).
// ---------------------------------------------------------------------------
__global__ void __launch_bounds__(256)
rx_a(const float* __restrict__ phi, const float* __restrict__ thetas)
{
    __shared__ float sm[8][34 * 32];
    const int w    = threadIdx.x >> 5;
    const int lane = threadIdx.x & 31;
    const u32 gw   = blockIdx.x * 8 + w;       // 16384 warps
    const int b    = gw >> 10;
    const u32 base = gw << 10;

    float t1[5], t2[5];
    float C1 = load_tc<5>(thetas, b, 0, t1);
    float C2 = load_tc<5>(thetas, b, 5, t2);
    const float Ct = C1 * C2;

    u64 PX[16], PY[16];
    const float4* p4 = reinterpret_cast<const float4*>(phi + base + lane * 32);
#pragma unroll
    for (int k = 0; k < 8; ++k) {
        float4 v = __ldcs(p4 + k);
        PX[2 * k]     = pk(v.x, v.y);
        PX[2 * k + 1] = pk(v.z, v.w);
    }

    // specialized stage 0 with imag = 0: PX unchanged, PY = -t * swap(PX)
    {
        const float tn = -t1[0];
#pragma unroll
        for (int q = 0; q < 16; ++q) {
            float xl, xh; upk(PX[q], xl, xh);
            PY[q] = pk(tn * xh, tn * xl);
        }
    }
    fg_tail<16, 4>(PX, PY, t1);    // bits 1..4

    float* X = sm[w];
#pragma unroll
    for (int q = 0; q < 16; ++q) {
        float l, h; upk(PX[q], l, h);
        X[(2 * q) * 34 + lane]     = l;
        X[(2 * q + 1) * 34 + lane] = h;
    }
    __syncwarp();
#pragma unroll
    for (int q = 0; q < 16; ++q) {
        float2 v = *reinterpret_cast<float2*>(&X[lane * 34 + 2 * q]);
        PX[q] = pk(v.x, v.y);
    }
    __syncwarp();
#pragma unroll
    for (int q = 0; q < 16; ++q) {
        float l, h; upk(PY[q], l, h);
        X[(2 * q) * 34 + lane]     = l;
        X[(2 * q + 1) * 34 + lane] = h;
    }
    __syncwarp();
#pragma unroll
    for (int q = 0; q < 16; ++q) {
        float2 v = *reinterpret_cast<float2*>(&X[lane * 34 + 2 * q]);
        PY[q] = pk(v.x, v.y);
    }

    fg_stage0<16>(PX, PY, t2[0]);  // bit 5
    fg_tail<16, 4>(PX, PY, t2);    // bits 6..9

    fg_scale<16>(PX, PY, Ct);

#pragma unroll
    for (int q = 0; q < 16; ++q) {
        float xl, xh, yl, yh;
        upk(PX[q], xl, xh); upk(PY[q], yl, yh);
        __half2 h0 = __floats2half2_rn(xl, yl);
        __half2 h1 = __floats2half2_rn(xh, yh);
        g_scratch[base + (2 * q) * 32 + lane]     = *reinterpret_cast<u32*>(&h0);
        g_scratch[base + (2 * q + 1) * 32 + lane] = *reinterpret_cast<u32*>(&h1);
    }
}

// ---------------------------------------------------------------------------
// Pass B v3: global bits 10..19, all 16 batches.
// 512 threads, 16 elem/thread (16-reg state) -> 2 CTAs/SM = 32 warps/SM.
// 3 register phases: bits 10..13, 14..17, 18..19, with two conflict-free
// padded smem transposes (2 barriers total; transpose-2 reuses transpose-1's
// slots thread-privately, so no barrier between read1 and store2).
// thread: low3 = t&7, g6 = t>>3.
//   phase1: g6 = bits 14..19, regs = bits 10..13
//   phase2: g6 = (bits18..19)<<4 | (bits10..13), regs = bits 14..17
//   phase3: g6 = (bits12..13)<<4 | (bits14..17), regs = (bits18..19, bits10..11)
// smem slot (fp32): idx = (bits14..19)*136 + (bits10..13)*8 + low3
// ---------------------------------------------------------------------------
__global__ void __launch_bounds__(512, 2)
rx_b(const float* __restrict__ thetas, float2* __restrict__ out)
{
    __shared__ float smX[64 * 136];            // 34816 B
    __shared__ float smY[64 * 136];            // 34816 B
    const int t   = threadIdx.x;
    const int low = t & 7;
    const int g6  = t >> 3;                    // 0..63
    const int blk   = blockIdx.x;              // 2048 blocks
    const int b     = blk >> 7;
    const int chunk = blk & 127;
    const u32 base  = ((u32)b << 20) + ((u32)chunk << 3) + (u32)low;

    float t1[4];
    float C1 = load_tc<4>(thetas, b, 10, t1);

    // ---- phase 1: regs = bits 10..13 (g6 = bits 14..19) ----
    u64 PX[8], PY[8];
    const u32 a0 = base + ((u32)g6 << 14);
#pragma unroll
    for (int h = 0; h < 2; ++h) {              // two half-batches of 8 (MLP)
        u32 wv[8];
#pragma unroll
        for (int k = 0; k < 8; ++k)
            wv[k] = __ldcs(&g_scratch[a0 + ((u32)(h * 8 + k) << 10)]);
#pragma unroll
        for (int k = 0; k < 4; ++k) {
            const int q = h * 4 + k;
            float2 v0 = __half22float2(*reinterpret_cast<__half2*>(&wv[2 * k]));
            float2 v1 = __half22float2(*reinterpret_cast<__half2*>(&wv[2 * k + 1]));
            PX[q] = pk(v0.x, v1.x);
            PY[q] = pk(v0.y, v1.y);
        }
    }

    fg_stage0<8>(PX, PY, t1[0]);               // bit 10
    fg_tail<8, 3>(PX, PY, t1);                 // bits 11..13

    // ---- transpose 1: store (g6, j4, low) ----
#pragma unroll
    for (int q = 0; q < 8; ++q) {
        float xl, xh, yl, yh;
        upk(PX[q], xl, xh); upk(PY[q], yl, yh);
        smX[g6 * 136 + (2 * q) * 8 + low]     = xl;
        smX[g6 * 136 + (2 * q + 1) * 8 + low] = xh;
        smY[g6 * 136 + (2 * q) * 8 + low]     = yl;
        smY[g6 * 136 + (2 * q + 1) * 8 + low] = yh;
    }
    __syncthreads();

    // ---- phase 2: regs = bits 14..17; thread fixed h2 = bits18..19, f4 = bits10..13
    const int h2 = g6 >> 4;
    const int f4 = g6 & 15;
    const int rbase = f4 * 8 + low;
#pragma unroll
    for (int q = 0; q < 8; ++q) {
        PX[q] = pk(smX[(h2 * 16 + 2 * q) * 136 + rbase],
                   smX[(h2 * 16 + 2 * q + 1) * 136 + rbase]);
        PY[q] = pk(smY[(h2 * 16 + 2 * q) * 136 + rbase],
                   smY[(h2 * 16 + 2 * q + 1) * 136 + rbase]);
    }

    float t2[4];
    float C2 = load_tc<4>(thetas, b, 14, t2);
    fg_stage0<8>(PX, PY, t2[0]);               // bit 14
    fg_tail<8, 3>(PX, PY, t2);                 // bits 15..17

    // ---- transpose 2: write back to the SAME slots (thread-private; no
    //      barrier needed before, one after) ----
#pragma unroll
    for (int q = 0; q < 8; ++q) {
        float xl, xh, yl, yh;
        upk(PX[q], xl, xh); upk(PY[q], yl, yh);
        smX[(h2 * 16 + 2 * q) * 136 + rbase]     = xl;
        smX[(h2 * 16 + 2 * q + 1) * 136 + rbase] = xh;
        smY[(h2 * 16 + 2 * q) * 136 + rbase]     = yl;
        smY[(h2 * 16 + 2 * q + 1) * 136 + rbase] = yh;
    }
    __syncthreads();

    // ---- phase 3: regs r = (bits18..19)<<2 | (bits10..11);
    //      thread fixed c2 = bits12..13, f4p = bits14..17
    const int c2  = g6 >> 4;
    const int f4p = g6 & 15;
#pragma unroll
    for (int q = 0; q < 8; ++q) {
        const int rA = 2 * q, rB = 2 * q + 1;
        const int iA = (((rA >> 2) * 16 + f4p) * 136) + (c2 * 4 + (rA & 3)) * 8 + low;
        const int iB = (((rB >> 2) * 16 + f4p) * 136) + (c2 * 4 + (rB & 3)) * 8 + low;
        PX[q] = pk(smX[iA], smX[iB]);
        PY[q] = pk(smY[iA], smY[iB]);
    }

    float t3[2];
    float C3 = load_tc<2>(thetas, b, 18, t3);
    fg_mask<8>(PX, PY, t3[0], 2);              // bit 18 (r bit 2 -> pack mask 2)
    fg_mask<8>(PX, PY, t3[1], 4);              // bit 19 (r bit 3 -> pack mask 4)

    fg_scale<8>(PX, PY, C1 * C2 * C3);

    // ---- store: element = base + h2<<18 | f4p<<14 | c2<<12 | d2<<10 ----
    const u32 a1 = base + ((u32)f4p << 14) + ((u32)c2 << 12);
#pragma unroll
    for (int q = 0; q < 8; ++q) {
        const int rA = 2 * q, rB = 2 * q + 1;
        float xl, xh, yl, yh;
        upk(PX[q], xl, xh); upk(PY[q], yl, yh);
        __stcs(&out[a1 + ((u32)(rA >> 2) << 18) + ((u32)(rA & 3) << 10)],
               make_float2(xl, yl));
        __stcs(&out[a1 + ((u32)(rB >> 2) << 18) + ((u32)(rB & 3) << 10)],
               make_float2(xh, yh));
    }
}

// ---------------------------------------------------------------------------
extern "C" void kernel_launch(void* const* d_in, const int* in_sizes, int n_in,
                              void* d_out, int out_size)
{
    const float* phi    = (const float*)d_in[0];   // [16, 2^20] float32
    const float* thetas = (const float*)d_in[1];   // [16, 20]   float32
    float2* out = (float2*)d_out;                  // [16, 2^20] (re, im)

    rx_a<<<2048, 256>>>(phi, thetas);
    rx_b<<<2048, 512>>>(thetas, out);
}

// round 11
// speedup vs baseline: 1.0545x; 1.0545x over previous
#include <cuda_runtime.h>
#include <cuda_fp16.h>

#define NQ 20
typedef unsigned long long u64;
typedef unsigned int u32;

// 64MB scratch: fp16x2 intermediate for all 16 batches
__device__ u32 g_scratch[16u << 20];

// ---------------- f32x2 helpers (packed 2xfp32 ops, sm_103a) ----------------
__device__ __forceinline__ u64 pk(float lo, float hi) {
    u64 r; asm("mov.b64 %0,{%1,%2};" : "=l"(r) : "f"(lo), "f"(hi)); return r;
}
__device__ __forceinline__ void upk(u64 p, float& lo, float& hi) {
    asm("mov.b64 {%0,%1},%2;" : "=f"(lo), "=f"(hi) : "l"(p));
}
__device__ __forceinline__ u64 f2mul(u64 a, u64 b) {
    u64 r; asm("mul.rn.f32x2 %0,%1,%2;" : "=l"(r) : "l"(a), "l"(b)); return r;
}
__device__ __forceinline__ u64 f2fma(u64 a, u64 b, u64 c) {
    u64 r; asm("fma.rn.f32x2 %0,%1,%2,%3;" : "=l"(r) : "l"(a), "l"(b), "l"(c)); return r;
}

// ---------------- fast-Givens RX stages ----------------
// Unscaled update with t = tan(th/2):
//   ax' = ax + t*by ; ay' = ay - t*bx ; bx' = bx + t*ay ; by' = by - t*ax
// True result = (prod of cos) * unscaled; scale applied once at the end.

template<int NP>
__device__ __forceinline__ void fg_stage0(u64* PX, u64* PY, float tt)
{
#pragma unroll
    for (int q = 0; q < NP; ++q) {
        float xl, xh, yl, yh;
        upk(PX[q], xl, xh); upk(PY[q], yl, yh);
        PX[q] = pk(fmaf(tt, yh, xl), fmaf(tt, yl, xh));
        PY[q] = pk(fmaf(-tt, xh, yl), fmaf(-tt, xl, yh));
    }
}

template<int NP>
__device__ __forceinline__ void fg_mask(u64* PX, u64* PY, float tv, int pm)
{
    u64 t2  = pk(tv,  tv);
    u64 tn2 = pk(-tv, -tv);
#pragma unroll
    for (int q = 0; q < NP; ++q) {
        if (!(q & pm)) {
            const int q2 = q | pm;
            u64 ax = PX[q], bx = PX[q2];
            PX[q]  = f2fma(t2,  PY[q2], ax);
            PX[q2] = f2fma(t2,  PY[q],  bx);
            PY[q]  = f2fma(tn2, bx, PY[q]);
            PY[q2] = f2fma(tn2, ax, PY[q2]);
        }
    }
}

template<int NP, int JMAX>
__device__ __forceinline__ void fg_tail(u64* PX, u64* PY, const float* t)
{
#pragma unroll
    for (int j = 1; j <= JMAX; ++j)
        fg_mask<NP>(PX, PY, t[j], 1 << (j - 1));
}

template<int NP>
__device__ __forceinline__ void fg_scale(u64* PX, u64* PY, float C)
{
    u64 C2 = pk(C, C);
#pragma unroll
    for (int q = 0; q < NP; ++q) {
        PX[q] = f2mul(C2, PX[q]);
        PY[q] = f2mul(C2, PY[q]);
    }
}

// qubit i = most-significant bit => global bit g maps to theta index (19-g)
template<int N>
__device__ __forceinline__ float load_tc(const float* __restrict__ thetas, int b,
                                         int gbase, float* t)
{
    float C = 1.0f;
#pragma unroll
    for (int j = 0; j < N; ++j) {
        float th = thetas[b * NQ + (NQ - 1 - (gbase + j))];
        float s, c;
        __sincosf(0.5f * th, &s, &c);
        t[j] = __fdividef(s, c);
        C *= c;
    }
    return C;
}

// ---------------------------------------------------------------------------
// Pass A (unchanged from the 70.4us config): global bits 0..9, all 16
// batches. Warp owns 1024 contiguous elements. phi streamed in (__ldcs);
// fp16x2 intermediate to scratch.
// ---------------------------------------------------------------------------
__global__ void __launch_bounds__(256)
rx_a(const float* __restrict__ phi, const float* __restrict__ thetas)
{
    __shared__ float sm[8][34 * 32];
    const int w    = threadIdx.x >> 5;
    const int lane = threadIdx.x & 31;
    const u32 gw   = blockIdx.x * 8 + w;       // 16384 warps
    const int b    = gw >> 10;
    const u32 base = gw << 10;

    float t1[5], t2[5];
    float C1 = load_tc<5>(thetas, b, 0, t1);
    float C2 = load_tc<5>(thetas, b, 5, t2);
    const float Ct = C1 * C2;

    u64 PX[16], PY[16];
    const float4* p4 = reinterpret_cast<const float4*>(phi + base + lane * 32);
#pragma unroll
    for (int k = 0; k < 8; ++k) {
        float4 v = __ldcs(p4 + k);
        PX[2 * k]     = pk(v.x, v.y);
        PX[2 * k + 1] = pk(v.z, v.w);
    }

    // specialized stage 0 with imag = 0: PX unchanged, PY = -t * swap(PX)
    {
        const float tn = -t1[0];
#pragma unroll
        for (int q = 0; q < 16; ++q) {
            float xl, xh; upk(PX[q], xl, xh);
            PY[q] = pk(tn * xh, tn * xl);
        }
    }
    fg_tail<16, 4>(PX, PY, t1);    // bits 1..4

    float* X = sm[w];
#pragma unroll
    for (int q = 0; q < 16; ++q) {
        float l, h; upk(PX[q], l, h);
        X[(2 * q) * 34 + lane]     = l;
        X[(2 * q + 1) * 34 + lane] = h;
    }
    __syncwarp();
#pragma unroll
    for (int q = 0; q < 16; ++q) {
        float2 v = *reinterpret_cast<float2*>(&X[lane * 34 + 2 * q]);
        PX[q] = pk(v.x, v.y);
    }
    __syncwarp();
#pragma unroll
    for (int q = 0; q < 16; ++q) {
        float l, h; upk(PY[q], l, h);
        X[(2 * q) * 34 + lane]     = l;
        X[(2 * q + 1) * 34 + lane] = h;
    }
    __syncwarp();
#pragma unroll
    for (int q = 0; q < 16; ++q) {
        float2 v = *reinterpret_cast<float2*>(&X[lane * 34 + 2 * q]);
        PY[q] = pk(v.x, v.y);
    }

    fg_stage0<16>(PX, PY, t2[0]);  // bit 5
    fg_tail<16, 4>(PX, PY, t2);    // bits 6..9

    fg_scale<16>(PX, PY, Ct);

#pragma unroll
    for (int q = 0; q < 16; ++q) {
        float xl, xh, yl, yh;
        upk(PX[q], xl, xh); upk(PY[q], yl, yh);
        __half2 h0 = __floats2half2_rn(xl, yl);
        __half2 h1 = __floats2half2_rn(xh, yh);
        g_scratch[base + (2 * q) * 32 + lane]     = *reinterpret_cast<u32*>(&h0);
        g_scratch[base + (2 * q + 1) * 32 + lane] = *reinterpret_cast<u32*>(&h1);
    }
}

// ---------------------------------------------------------------------------
// Pass B v4: global bits 10..19, all 16 batches. 2-phase, wide-lane.
// 512 threads: low = t&15 (16 consecutive -> 64B loads, 128B stores),
// g5 = t>>4 (5 bits). Block covers 16 low x 1024 high = 16384 elements.
//   phase1: g5 = bits 15..19, regs r = bits 10..14
//   phase2: g5 = bits 10..14, regs r' = bits 15..19
// Dynamic smem transpose buffers X, Y: slot(i5=bits15..19, j5=bits10..14, low)
//   idx = i5*528 + j5*16 + low  (528 % 32 == 16 -> conflict-free both ways)
// One __syncthreads.
// ---------------------------------------------------------------------------
#define RXB_PAD 528
#define RXB_SMEM_FLOATS (32 * RXB_PAD)
#define RXB_SMEM_BYTES  (2 * RXB_SMEM_FLOATS * 4)

__global__ void __launch_bounds__(512, 1)
rx_b(const float* __restrict__ thetas, float2* __restrict__ out)
{
    extern __shared__ float dsm[];
    float* smX = dsm;
    float* smY = dsm + RXB_SMEM_FLOATS;

    const int t   = threadIdx.x;
    const int low = t & 15;
    const int g5  = t >> 4;                    // 0..31
    const int blk   = blockIdx.x;              // 1024 blocks
    const int b     = blk >> 6;                // batch
    const int chunk = blk & 63;                // low bits 4..9
    const u32 base  = ((u32)b << 20) + ((u32)chunk << 4) + (u32)low;

    float t1[5];
    float C1 = load_tc<5>(thetas, b, 10, t1);

    // ---- phase 1: regs = bits 10..14 (g5 = bits 15..19) ----
    u64 PX[16], PY[16];
    const u32 a0 = base + ((u32)g5 << 15);
#pragma unroll
    for (int h = 0; h < 2; ++h) {              // two batches of 16 loads (MLP)
        u32 wv[16];
#pragma unroll
        for (int k = 0; k < 16; ++k)
            wv[k] = __ldcs(&g_scratch[a0 + ((u32)(h * 16 + k) << 10)]);
#pragma unroll
        for (int k = 0; k < 8; ++k) {
            const int q = h * 8 + k;
            float2 v0 = __half22float2(*reinterpret_cast<__half2*>(&wv[2 * k]));
            float2 v1 = __half22float2(*reinterpret_cast<__half2*>(&wv[2 * k + 1]));
            PX[q] = pk(v0.x, v1.x);
            PY[q] = pk(v0.y, v1.y);
        }
    }

    fg_stage0<16>(PX, PY, t1[0]);              // bit 10
    fg_tail<16, 4>(PX, PY, t1);                // bits 11..14

    // ---- transpose store: idx = g5*528 + r*16 + low ----
#pragma unroll
    for (int q = 0; q < 16; ++q) {
        float xl, xh, yl, yh;
        upk(PX[q], xl, xh); upk(PY[q], yl, yh);
        smX[g5 * RXB_PAD + (2 * q) * 16 + low]     = xl;
        smX[g5 * RXB_PAD + (2 * q + 1) * 16 + low] = xh;
        smY[g5 * RXB_PAD + (2 * q) * 16 + low]     = yl;
        smY[g5 * RXB_PAD + (2 * q + 1) * 16 + low] = yh;
    }
    __syncthreads();

    // ---- phase 2: regs = bits 15..19 (g5 now = bits 10..14) ----
    const int rb = g5 * 16 + low;
#pragma unroll
    for (int q = 0; q < 16; ++q) {
        PX[q] = pk(smX[(2 * q) * RXB_PAD + rb],
                   smX[(2 * q + 1) * RXB_PAD + rb]);
        PY[q] = pk(smY[(2 * q) * RXB_PAD + rb],
                   smY[(2 * q + 1) * RXB_PAD + rb]);
    }

    float t2[5];
    float C2 = load_tc<5>(thetas, b, 15, t2);
    fg_stage0<16>(PX, PY, t2[0]);              // bit 15
    fg_tail<16, 4>(PX, PY, t2);                // bits 16..19

    fg_scale<16>(PX, PY, C1 * C2);

    // ---- store: element = base + g5<<10 + r'<<15 ; 16 lanes -> 128B lines ----
    const u32 a1 = base + ((u32)g5 << 10);
#pragma unroll
    for (int q = 0; q < 16; ++q) {
        float xl, xh, yl, yh;
        upk(PX[q], xl, xh); upk(PY[q], yl, yh);
        __stcs(&out[a1 + ((u32)(2 * q) << 15)],     make_float2(xl, yl));
        __stcs(&out[a1 + ((u32)(2 * q + 1) << 15)], make_float2(xh, yh));
    }
}

// ---------------------------------------------------------------------------
extern "C" void kernel_launch(void* const* d_in, const int* in_sizes, int n_in,
                              void* d_out, int out_size)
{
    const float* phi    = (const float*)d_in[0];   // [16, 2^20] float32
    const float* thetas = (const float*)d_in[1];   // [16, 20]   float32
    float2* out = (float2*)d_out;                  // [16, 2^20] (re, im)

    static int smem_set = 0;
    if (!smem_set) {
        cudaFuncSetAttribute(rx_b, cudaFuncAttributeMaxDynamicSharedMemorySize,
                             RXB_SMEM_BYTES);
        smem_set = 1;
    }

    rx_a<<<2048, 256>>>(phi, thetas);
    rx_b<<<1024, 512, RXB_SMEM_BYTES>>>(thetas, out);
}